// round 3
// baseline (speedup 1.0000x reference)
#include <cuda_runtime.h>
#include <math.h>

// Problem constants
#define B_ROWS   1024
#define NFEAT    256
#define NSAMP    100000
#define INV_TEMP 20.0f     // 1 / 0.05

// Tiling
#define TM          128            // batch rows per CTA
#define TN          64             // samples per inner tile
#define CHUNK_TILES 21
#define CHUNK       (CHUNK_TILES * TN)   // 1344 samples per chunk
#define NCHUNK      75                   // 75 * 1344 = 100800 >= 100000
#define NROWTILES   (B_ROWS / TM)        // 8

#define AS_STRIDE 132   // padded row stride for k-major A tile (floats)
#define FS_STRIDE 257   // padded row stride for F tile (floats)

// Scratch (no device allocation allowed)
__device__ float2 g_partials[B_ROWS * NCHUNK];   // (running max, running sumexp)
__device__ float  g_nll[B_ROWS];

// ---------------------------------------------------------------------------
// Kernel 1: fused GEMM + online (max, sumexp) per (row, sample-chunk)
// ---------------------------------------------------------------------------
__global__ __launch_bounds__(256, 1)
void k_partial(const float* __restrict__ inputs, const float* __restrict__ feats)
{
    extern __shared__ float sm[];
    float* As = sm;                            // [NFEAT][AS_STRIDE], k-major
    float* Fs = sm + NFEAT * AS_STRIDE;        // [TN][FS_STRIDE],   s-major

    const int tid = threadIdx.x;
    const int tx  = tid & 15;   // 16 sample-groups (4 samples each) -> 64 samples
    const int ty  = tid >> 4;   // 16 row-groups    (8 rows each)    -> 128 rows

    const int r0 = blockIdx.y * TM;      // batch row base
    const int c0 = blockIdx.x * CHUNK;   // sample base of this chunk

    // ---- Load & transpose A tile: inputs[r0 .. r0+127][0..255] -> As[k][r]
    const float4* in4 = (const float4*)inputs;
    for (int i = tid; i < TM * (NFEAT / 4); i += 256) {
        int r = i >> 6;          // 64 float4 per row
        int c = i & 63;
        float4 v = in4[(size_t)(r0 + r) * (NFEAT / 4) + c];
        int k = c * 4;
        As[(k + 0) * AS_STRIDE + r] = v.x;
        As[(k + 1) * AS_STRIDE + r] = v.y;
        As[(k + 2) * AS_STRIDE + r] = v.z;
        As[(k + 3) * AS_STRIDE + r] = v.w;
    }
    __syncthreads();

    float rm[8], rs[8];
    #pragma unroll
    for (int i = 0; i < 8; i++) { rm[i] = -INFINITY; rs[i] = 0.0f; }

    const float4* f4 = (const float4*)feats;

    for (int t = 0; t < CHUNK_TILES; t++) {
        const int sbase = c0 + t * TN;

        __syncthreads();   // protect Fs against previous iteration's readers
        // ---- Load F tile: feats[sbase .. sbase+63][:] -> Fs[s][k] (padded)
        for (int i = tid; i < TN * (NFEAT / 4); i += 256) {
            int ss = i >> 6;
            int c  = i & 63;
            int gs = sbase + ss;
            float4 v = (gs < NSAMP) ? f4[(size_t)gs * (NFEAT / 4) + c]
                                    : make_float4(0.f, 0.f, 0.f, 0.f);
            int k = c * 4;
            float* dst = Fs + ss * FS_STRIDE + k;
            dst[0] = v.x; dst[1] = v.y; dst[2] = v.z; dst[3] = v.w;
        }
        __syncthreads();

        // ---- Compute 8x4 register tile of dot products over K=256
        float acc[8][4];
        #pragma unroll
        for (int i = 0; i < 8; i++)
            #pragma unroll
            for (int j = 0; j < 4; j++) acc[i][j] = 0.0f;

        const float* FsBase = Fs + (tx * 4) * FS_STRIDE;

        #pragma unroll 8
        for (int k = 0; k < NFEAT; k++) {
            const float4* Ak = (const float4*)(As + k * AS_STRIDE);
            float4 a0 = Ak[ty * 2 + 0];   // rows ty*8 + 0..3
            float4 a1 = Ak[ty * 2 + 1];   // rows ty*8 + 4..7
            float f0 = FsBase[0 * FS_STRIDE + k];
            float f1 = FsBase[1 * FS_STRIDE + k];
            float f2 = FsBase[2 * FS_STRIDE + k];
            float f3 = FsBase[3 * FS_STRIDE + k];

            acc[0][0] = fmaf(a0.x, f0, acc[0][0]);
            acc[0][1] = fmaf(a0.x, f1, acc[0][1]);
            acc[0][2] = fmaf(a0.x, f2, acc[0][2]);
            acc[0][3] = fmaf(a0.x, f3, acc[0][3]);
            acc[1][0] = fmaf(a0.y, f0, acc[1][0]);
            acc[1][1] = fmaf(a0.y, f1, acc[1][1]);
            acc[1][2] = fmaf(a0.y, f2, acc[1][2]);
            acc[1][3] = fmaf(a0.y, f3, acc[1][3]);
            acc[2][0] = fmaf(a0.z, f0, acc[2][0]);
            acc[2][1] = fmaf(a0.z, f1, acc[2][1]);
            acc[2][2] = fmaf(a0.z, f2, acc[2][2]);
            acc[2][3] = fmaf(a0.z, f3, acc[2][3]);
            acc[3][0] = fmaf(a0.w, f0, acc[3][0]);
            acc[3][1] = fmaf(a0.w, f1, acc[3][1]);
            acc[3][2] = fmaf(a0.w, f2, acc[3][2]);
            acc[3][3] = fmaf(a0.w, f3, acc[3][3]);
            acc[4][0] = fmaf(a1.x, f0, acc[4][0]);
            acc[4][1] = fmaf(a1.x, f1, acc[4][1]);
            acc[4][2] = fmaf(a1.x, f2, acc[4][2]);
            acc[4][3] = fmaf(a1.x, f3, acc[4][3]);
            acc[5][0] = fmaf(a1.y, f0, acc[5][0]);
            acc[5][1] = fmaf(a1.y, f1, acc[5][1]);
            acc[5][2] = fmaf(a1.y, f2, acc[5][2]);
            acc[5][3] = fmaf(a1.y, f3, acc[5][3]);
            acc[6][0] = fmaf(a1.z, f0, acc[6][0]);
            acc[6][1] = fmaf(a1.z, f1, acc[6][1]);
            acc[6][2] = fmaf(a1.z, f2, acc[6][2]);
            acc[6][3] = fmaf(a1.z, f3, acc[6][3]);
            acc[7][0] = fmaf(a1.w, f0, acc[7][0]);
            acc[7][1] = fmaf(a1.w, f1, acc[7][1]);
            acc[7][2] = fmaf(a1.w, f2, acc[7][2]);
            acc[7][3] = fmaf(a1.w, f3, acc[7][3]);
        }

        // ---- Online softmax update (per thread, per owned row)
        const int s_th = sbase + tx * 4;     // this thread's first sample
        bool v0 = (s_th + 0) < NSAMP;
        bool v1 = (s_th + 1) < NSAMP;
        bool v2 = (s_th + 2) < NSAMP;
        bool v3 = (s_th + 3) < NSAMP;

        if (v0) {   // if first is invalid, all are invalid (monotone)
            #pragma unroll
            for (int i = 0; i < 8; i++) {
                float l0 = acc[i][0] * INV_TEMP;
                float l1 = acc[i][1] * INV_TEMP;
                float l2 = acc[i][2] * INV_TEMP;
                float l3 = acc[i][3] * INV_TEMP;
                float tm = l0;
                if (v1) tm = fmaxf(tm, l1);
                if (v2) tm = fmaxf(tm, l2);
                if (v3) tm = fmaxf(tm, l3);
                float nm = fmaxf(rm[i], tm);
                float e = __expf(l0 - nm);
                if (v1) e += __expf(l1 - nm);
                if (v2) e += __expf(l2 - nm);
                if (v3) e += __expf(l3 - nm);
                rs[i] = rs[i] * __expf(rm[i] - nm) + e;
                rm[i] = nm;
            }
        }
    }

    // ---- Merge (m, s) across the 16 tx lanes (same 8 rows per ty group)
    #pragma unroll
    for (int off = 8; off >= 1; off >>= 1) {
        #pragma unroll
        for (int i = 0; i < 8; i++) {
            float om = __shfl_xor_sync(0xffffffffu, rm[i], off, 16);
            float os = __shfl_xor_sync(0xffffffffu, rs[i], off, 16);
            float nm = fmaxf(rm[i], om);
            rs[i] = rs[i] * __expf(rm[i] - nm) + os * __expf(om - nm);
            rm[i] = nm;
        }
    }

    if (tx == 0) {
        #pragma unroll
        for (int i = 0; i < 8; i++) {
            int row = r0 + ty * 8 + i;
            g_partials[(size_t)row * NCHUNK + blockIdx.x] = make_float2(rm[i], rs[i]);
        }
    }
}

// ---------------------------------------------------------------------------
// Kernel 2: per-row combine of chunk partials + exact target logit -> NLL
// targets is INT32 (JAX x64 disabled: jnp.int64 request silently yields int32)
// ---------------------------------------------------------------------------
__global__ void k_combine(const float* __restrict__ inputs,
                          const float* __restrict__ feats,
                          const int* __restrict__ targets)
{
    const int row = blockIdx.x;
    const int t   = threadIdx.x;    // 32 threads

    float m = -INFINITY, s = 0.0f;
    for (int c = t; c < NCHUNK; c += 32) {
        float2 p = g_partials[(size_t)row * NCHUNK + c];
        float nm = fmaxf(m, p.x);
        s = s * __expf(m - nm) + p.y * __expf(p.x - nm);
        m = nm;
    }
    #pragma unroll
    for (int off = 16; off >= 1; off >>= 1) {
        float om = __shfl_xor_sync(0xffffffffu, m, off);
        float os = __shfl_xor_sync(0xffffffffu, s, off);
        float nm = fmaxf(m, om);
        s = s * __expf(m - nm) + os * __expf(om - nm);
        m = nm;
    }

    // exact target logit (fp32 dot). Clamp defensively so a bad index can
    // never fault (would surface as rel_err instead, which is diagnosable).
    int tg = targets[row];
    tg = (tg < 0) ? 0 : ((tg >= NSAMP) ? (NSAMP - 1) : tg);
    const float* ir = inputs + (size_t)row * NFEAT;
    const float* fr = feats  + (size_t)tg  * NFEAT;
    float d = 0.0f;
    for (int k = t; k < NFEAT; k += 32) d = fmaf(ir[k], fr[k], d);
    #pragma unroll
    for (int off = 16; off >= 1; off >>= 1)
        d += __shfl_xor_sync(0xffffffffu, d, off);

    if (t == 0)
        g_nll[row] = (m + logf(s)) - d * INV_TEMP;
}

// ---------------------------------------------------------------------------
// Kernel 3: deterministic mean over rows -> out[0]
// ---------------------------------------------------------------------------
__global__ void k_mean(float* __restrict__ out)
{
    __shared__ float red[256];
    const int t = threadIdx.x;
    float a = 0.0f;
    for (int i = t; i < B_ROWS; i += 256) a += g_nll[i];
    red[t] = a;
    __syncthreads();
    for (int w = 128; w > 0; w >>= 1) {
        if (t < w) red[t] += red[t + w];
        __syncthreads();
    }
    if (t == 0) out[0] = red[0] * (1.0f / B_ROWS);
}

// ---------------------------------------------------------------------------
extern "C" void kernel_launch(void* const* d_in, const int* in_sizes, int n_in,
                              void* d_out, int out_size)
{
    const float* inputs  = (const float*)d_in[0];
    const int*   targets = (const int*)d_in[1];      // int32 (see k_combine note)
    const float* feats   = (const float*)d_in[2];

    const size_t smem = (size_t)(NFEAT * AS_STRIDE + TN * FS_STRIDE) * sizeof(float);
    cudaFuncSetAttribute(k_partial, cudaFuncAttributeMaxDynamicSharedMemorySize, (int)smem);

    dim3 grid(NCHUNK, NROWTILES);
    k_partial<<<grid, 256, smem>>>(inputs, feats);
    k_combine<<<B_ROWS, 32>>>(inputs, feats, targets);
    k_mean<<<1, 256>>>((float*)d_out);
}

// round 7
// speedup vs baseline: 3.2307x; 3.2307x over previous
#include <cuda_runtime.h>
#include <math.h>
#include <stdint.h>

// ---------------------------------------------------------------- constants
#define B_ROWS   1024
#define NFEAT    256
#define NSAMP    100000
#define INV_TEMP 20.0f
#define LOG2E    1.4426950408889634f
#define LN2      0.6931471805599453f
#define XSCALE   (INV_TEMP * LOG2E)      // logits computed in base-2 domain
#define CUT      40.0f                   // 2^-40 * 1e5 ~ 1e-7 relative: safe skip

#define TILE_N    128                    // samples per tile
#define TILES_TOT 782                    // ceil(100000/128)
#define NS_PAD    (TILES_TOT * TILE_N)   // 100096 (pad rows zeroed)
#define NCHUNK    9
#define TPC       87                     // ceil(782/9)
#define NROWT     16                     // 1024/64
#define M_CTA     64

// smem: A[64][260] fp32 + two B k-half buffers [128][132] fp32
#define A_STRIDE   260
#define B_STRIDE   132
#define A_FLOATS   (M_CTA * A_STRIDE)               // 16640
#define B_FLOATS   (TILE_N * B_STRIDE)              // 16896
#define SMEM_TOTAL ((A_FLOATS + 2 * B_FLOATS) * 4)  // 201728 bytes

// ---------------------------------------------------------------- scratch
__device__ float  g_ftf[(size_t)NS_PAD * NFEAT];     // tf32-rounded features (pad rows = 0)
__device__ float2 g_partials[B_ROWS * NCHUNK * 2];   // (m2, s2) per (row, chunk, n-half)
__device__ float  g_nll[B_ROWS];

// ---------------------------------------------------------------- helpers
__device__ __forceinline__ uint32_t f2tf32(float x) {
    uint32_t r; asm("cvt.rna.tf32.f32 %0, %1;" : "=r"(r) : "f"(x)); return r;
}
__device__ __forceinline__ float ex2(float x) {
    float r; asm("ex2.approx.f32 %0, %1;" : "=f"(r) : "f"(x)); return r;
}
__device__ __forceinline__ uint32_t smem_u32(const void* p) {
    uint32_t a;
    asm("{ .reg .u64 t; cvta.to.shared.u64 t, %1; cvt.u32.u64 %0, t; }" : "=r"(a) : "l"(p));
    return a;
}
__device__ __forceinline__ void mma_tf32(float* c, const uint32_t* a, uint32_t b0, uint32_t b1) {
    asm volatile(
        "mma.sync.aligned.m16n8k8.row.col.f32.tf32.tf32.f32 "
        "{%0,%1,%2,%3}, {%4,%5,%6,%7}, {%8,%9}, {%0,%1,%2,%3};"
        : "+f"(c[0]), "+f"(c[1]), "+f"(c[2]), "+f"(c[3])
        : "r"(a[0]), "r"(a[1]), "r"(a[2]), "r"(a[3]), "r"(b0), "r"(b1));
}
#define CP_COMMIT() asm volatile("cp.async.commit_group;" ::: "memory")
#define CP_WAIT1()  asm volatile("cp.async.wait_group 1;"  ::: "memory")
#define CP_WAIT0()  asm volatile("cp.async.wait_group 0;"  ::: "memory")

// ---------------------------------------------------------------- convert features -> tf32 (pad rows zero)
__global__ void k_convert_feats(const float* __restrict__ feats)
{
    const float4* f4 = (const float4*)feats;
    float4* o4 = (float4*)g_ftf;
    const int n4 = NS_PAD * NFEAT / 4;
    for (int i = blockIdx.x * blockDim.x + threadIdx.x; i < n4; i += gridDim.x * blockDim.x) {
        int row = i >> 6;                       // 64 float4 per row
        float4 o;
        if (row < NSAMP) {
            float4 v = f4[i];
            o.x = __uint_as_float(f2tf32(v.x));
            o.y = __uint_as_float(f2tf32(v.y));
            o.z = __uint_as_float(f2tf32(v.z));
            o.w = __uint_as_float(f2tf32(v.w));
        } else {
            o = make_float4(0.f, 0.f, 0.f, 0.f);
        }
        o4[i] = o;
    }
}

// ---------------------------------------------------------------- B k-half async load
__device__ __forceinline__ void ld_half(float* buf, int gt, int kh, int tid)
{
    const float* src = g_ftf + (size_t)gt * TILE_N * NFEAT + kh * 128;
    const uint32_t sbase = smem_u32(buf);
    #pragma unroll
    for (int i = 0; i < 32; i++) {
        int c  = i * 128 + tid;                 // float4 slot, coalesced in tid
        int rr = c >> 5;                        // 32 float4 per 128-col half-row
        int cc = c & 31;
        uint32_t sa = sbase + (uint32_t)(rr * B_STRIDE + cc * 4) * 4u;
        const float* ga = src + (size_t)rr * NFEAT + cc * 4;
        asm volatile("cp.async.cg.shared.global [%0], [%1], 16;"
                     :: "r"(sa), "l"(ga) : "memory");
    }
}

// ---------------------------------------------------------------- main fused kernel
__global__ __launch_bounds__(128, 1)
void k_main(const float* __restrict__ inputs)
{
    extern __shared__ float sm[];
    float* As  = sm;                        // [64][260]
    float* Bs0 = sm + A_FLOATS;             // [128][132] k-half buffer 0
    float* Bs1 = Bs0 + B_FLOATS;            // [128][132] k-half buffer 1

    const int tid = threadIdx.x;
    const int wid = tid >> 5;
    const int ln  = tid & 31;
    const int wm  = wid >> 1;               // m-half: rows wm*32 .. +31
    const int wn  = wid & 1;                // n-half: cols wn*64 .. +63
    const int lg  = ln >> 2;                // mma groupID 0..7
    const int lt  = ln & 3;                 // mma tid-in-group 0..3

    const int r0  = blockIdx.x * M_CTA;
    const int gt0 = blockIdx.y * TPC;
    int T = TILES_TOT - gt0; if (T > TPC) T = TPC;

    // ---- load A: inputs * XSCALE, tf32-rounded, into padded smem
    {
        const float4* in4 = (const float4*)inputs;
        for (int i = tid; i < M_CTA * 64; i += 128) {
            int rr = i >> 6, cc = i & 63;
            float4 v = in4[(size_t)(r0 + rr) * 64 + cc];
            uint32_t* dst = (uint32_t*)(As + rr * A_STRIDE + cc * 4);
            dst[0] = f2tf32(v.x * XSCALE);
            dst[1] = f2tf32(v.y * XSCALE);
            dst[2] = f2tf32(v.z * XSCALE);
            dst[3] = f2tf32(v.w * XSCALE);
        }
    }

    // ---- prologue: async-load first tile's two k-halves
    ld_half(Bs0, gt0, 0, tid); CP_COMMIT();
    ld_half(Bs1, gt0, 1, tid); CP_COMMIT();

    float acc[2][8][4];
    #pragma unroll
    for (int mf = 0; mf < 2; mf++)
        #pragma unroll
        for (int nf = 0; nf < 8; nf++)
            #pragma unroll
            for (int j = 0; j < 4; j++) acc[mf][nf][j] = 0.0f;

    float m[4], s[4];   // per owned row slot: r = mf*2+hh
    #pragma unroll
    for (int r = 0; r < 4; r++) { m[r] = -3.0e38f; s[r] = 0.0f; }

    const uint32_t* Ap = (const uint32_t*)As;
    const int H = 2 * T;

    for (int h = 0; h < H; h++) {
        if (h + 1 < H) CP_WAIT1(); else CP_WAIT0();   // half h resident
        __syncthreads();

        const uint32_t* Bp = (const uint32_t*)((h & 1) ? Bs1 : Bs0);
        const int kh = h & 1;

        #pragma unroll
        for (int ks = 0; ks < 16; ks++) {
            const int kc = kh * 128 + ks * 8 + lt;
            uint32_t a[2][4];
            #pragma unroll
            for (int mf = 0; mf < 2; mf++) {
                const int rb = wm * 32 + mf * 16 + lg;
                a[mf][0] = Ap[rb * A_STRIDE + kc];
                a[mf][1] = Ap[(rb + 8) * A_STRIDE + kc];
                a[mf][2] = Ap[rb * A_STRIDE + kc + 4];
                a[mf][3] = Ap[(rb + 8) * A_STRIDE + kc + 4];
            }
            const int kb = ks * 8 + lt;
            #pragma unroll
            for (int nf = 0; nf < 8; nf++) {
                const int nn = wn * 64 + nf * 8 + lg;
                uint32_t b0 = Bp[nn * B_STRIDE + kb];
                uint32_t b1 = Bp[nn * B_STRIDE + kb + 4];
                mma_tf32(acc[0][nf], a[0], b0, b1);
                mma_tf32(acc[1][nf], a[1], b0, b1);
            }
        }

        __syncthreads();                    // all warps done reading this buffer
        if (h + 2 < H) {                    // refill the buffer just consumed
            ld_half((h & 1) ? Bs1 : Bs0, gt0 + ((h + 2) >> 1), (h + 2) & 1, tid);
            CP_COMMIT();
        }

        if (h & 1) {
            // ---- tile epilogue: threshold-gated online logsumexp (base-2)
            #pragma unroll
            for (int mf = 0; mf < 2; mf++) {
                #pragma unroll
                for (int hh = 0; hh < 2; hh++) {
                    const int r = mf * 2 + hh;
                    float t0 = fmaxf(acc[mf][0][2*hh], acc[mf][0][2*hh+1]);
                    float t1 = fmaxf(acc[mf][1][2*hh], acc[mf][1][2*hh+1]);
                    float t2 = fmaxf(acc[mf][2][2*hh], acc[mf][2][2*hh+1]);
                    float t3 = fmaxf(acc[mf][3][2*hh], acc[mf][3][2*hh+1]);
                    float t4 = fmaxf(acc[mf][4][2*hh], acc[mf][4][2*hh+1]);
                    float t5 = fmaxf(acc[mf][5][2*hh], acc[mf][5][2*hh+1]);
                    float t6 = fmaxf(acc[mf][6][2*hh], acc[mf][6][2*hh+1]);
                    float t7 = fmaxf(acc[mf][7][2*hh], acc[mf][7][2*hh+1]);
                    float tmax = fmaxf(fmaxf(fmaxf(t0, t1), fmaxf(t2, t3)),
                                       fmaxf(fmaxf(t4, t5), fmaxf(t6, t7)));
                    if (tmax > m[r] - CUT) {        // rare slow path
                        float nm = fmaxf(m[r], tmax);
                        float add = 0.0f;
                        #pragma unroll
                        for (int nf = 0; nf < 8; nf++) {
                            add += ex2(acc[mf][nf][2*hh]   - nm);
                            add += ex2(acc[mf][nf][2*hh+1] - nm);
                        }
                        s[r] = s[r] * ex2(m[r] - nm) + add;
                        m[r] = nm;
                    }
                }
            }
            #pragma unroll
            for (int mf = 0; mf < 2; mf++)
                #pragma unroll
                for (int nf = 0; nf < 8; nf++)
                    #pragma unroll
                    for (int j = 0; j < 4; j++) acc[mf][nf][j] = 0.0f;
        }
    }

    // ---- merge (m,s) across the 4 lanes (lt) sharing each row; store per n-half
    #pragma unroll
    for (int r = 0; r < 4; r++) {
        float mm = m[r], ss = s[r];
        #pragma unroll
        for (int off = 1; off <= 2; off <<= 1) {
            float om = __shfl_xor_sync(0xffffffffu, mm, off);
            float os = __shfl_xor_sync(0xffffffffu, ss, off);
            float nm = fmaxf(mm, om);
            ss = ss * ex2(mm - nm) + os * ex2(om - nm);
            mm = nm;
        }
        if (lt == 0) {
            const int row = r0 + wm * 32 + (r >> 1) * 16 + (r & 1) * 8 + lg;
            g_partials[((size_t)row * NCHUNK + blockIdx.y) * 2 + wn] = make_float2(mm, ss);
        }
    }
}

// ---------------------------------------------------------------- combine + mean
__global__ void k_combine(const float* __restrict__ inputs,
                          const float* __restrict__ feats,
                          const int* __restrict__ targets)
{
    const int row = blockIdx.x;
    const int t   = threadIdx.x;

    float m = -3.0e38f, s = 0.0f;                  // base-2
    for (int c = t; c < NCHUNK * 2; c += 32) {
        float2 p = g_partials[(size_t)row * NCHUNK * 2 + c];
        float nm = fmaxf(m, p.x);
        s = s * ex2(m - nm) + p.y * ex2(p.x - nm);
        m = nm;
    }
    #pragma unroll
    for (int off = 16; off >= 1; off >>= 1) {
        float om = __shfl_xor_sync(0xffffffffu, m, off);
        float os = __shfl_xor_sync(0xffffffffu, s, off);
        float nm = fmaxf(m, om);
        s = s * ex2(m - nm) + os * ex2(om - nm);
        m = nm;
    }

    // exact target logit in fp32
    int tg = targets[row];
    tg = (tg < 0) ? 0 : ((tg >= NSAMP) ? (NSAMP - 1) : tg);
    const float* ir = inputs + (size_t)row * NFEAT;
    const float* fr = feats  + (size_t)tg  * NFEAT;
    float d = 0.0f;
    for (int k = t; k < NFEAT; k += 32) d = fmaf(ir[k], fr[k], d);
    #pragma unroll
    for (int off = 16; off >= 1; off >>= 1)
        d += __shfl_xor_sync(0xffffffffu, d, off);

    if (t == 0)
        g_nll[row] = LN2 * (m + log2f(s)) - d * INV_TEMP;
}

__global__ void k_mean(float* __restrict__ out)
{
    __shared__ float red[256];
    const int t = threadIdx.x;
    float a = 0.0f;
    for (int i = t; i < B_ROWS; i += 256) a += g_nll[i];
    red[t] = a;
    __syncthreads();
    for (int w = 128; w > 0; w >>= 1) {
        if (t < w) red[t] += red[t + w];
        __syncthreads();
    }
    if (t == 0) out[0] = red[0] * (1.0f / B_ROWS);
}

// ---------------------------------------------------------------- launch
extern "C" void kernel_launch(void* const* d_in, const int* in_sizes, int n_in,
                              void* d_out, int out_size)
{
    const float* inputs  = (const float*)d_in[0];
    const int*   targets = (const int*)d_in[1];
    const float* feats   = (const float*)d_in[2];

    cudaFuncSetAttribute(k_main, cudaFuncAttributeMaxDynamicSharedMemorySize, SMEM_TOTAL);

    k_convert_feats<<<2048, 256>>>(feats);

    dim3 grid(NROWT, NCHUNK);               // row-tile fastest -> B shared in L2
    k_main<<<grid, 128, SMEM_TOTAL>>>(inputs);

    k_combine<<<B_ROWS, 32>>>(inputs, feats, targets);
    k_mean<<<1, 256>>>((float*)d_out);
}

// round 8
// speedup vs baseline: 3.7836x; 1.1711x over previous
#include <cuda_runtime.h>
#include <math.h>
#include <stdint.h>

// ---------------------------------------------------------------- constants
#define B_ROWS   1024
#define NFEAT    256
#define NSAMP    100000
#define INV_TEMP 20.0f
#define LOG2E    1.4426950408889634f
#define LN2      0.6931471805599453f
#define XSCALE   (INV_TEMP * LOG2E)      // logits computed in base-2 domain
#define CUT      40.0f                   // 2^-40 * 1e5 ~ 1e-7 relative: safe skip

#define TILE_N    128                    // samples per tile
#define TILES_TOT 782                    // ceil(100000/128)
#define NS_PAD    (TILES_TOT * TILE_N)   // 100096 (pad rows zeroed)
#define NCHUNK    18
#define TPC       44                     // ceil(782/18)
#define M_CTA     128
#define NROWT     8                      // 1024/128
#define THREADS   256

// smem: A[128][260] fp32 + two B k-quarter buffers [128][68] fp32
#define A_STRIDE   260
#define BQ_STRIDE  68
#define A_FLOATS   (M_CTA * A_STRIDE)                 // 33280
#define BQ_FLOATS  (TILE_N * BQ_STRIDE)               // 8704
#define SMEM_TOTAL ((A_FLOATS + 2 * BQ_FLOATS) * 4)   // 202752 bytes

// ---------------------------------------------------------------- scratch
__device__ float  g_ftf[(size_t)NS_PAD * NFEAT];     // tf32-rounded features (pad rows = 0)
__device__ float2 g_partials[B_ROWS * NCHUNK * 2];   // (m2, s2) per (row, chunk, n-half)
__device__ float  g_nll[B_ROWS];

// ---------------------------------------------------------------- helpers
__device__ __forceinline__ uint32_t f2tf32(float x) {
    uint32_t r; asm("cvt.rna.tf32.f32 %0, %1;" : "=r"(r) : "f"(x)); return r;
}
__device__ __forceinline__ float ex2(float x) {
    float r; asm("ex2.approx.f32 %0, %1;" : "=f"(r) : "f"(x)); return r;
}
__device__ __forceinline__ uint32_t smem_u32(const void* p) {
    uint32_t a;
    asm("{ .reg .u64 t; cvta.to.shared.u64 t, %1; cvt.u32.u64 %0, t; }" : "=r"(a) : "l"(p));
    return a;
}
__device__ __forceinline__ void mma_tf32(float* c, const uint32_t* a, uint32_t b0, uint32_t b1) {
    asm volatile(
        "mma.sync.aligned.m16n8k8.row.col.f32.tf32.tf32.f32 "
        "{%0,%1,%2,%3}, {%4,%5,%6,%7}, {%8,%9}, {%0,%1,%2,%3};"
        : "+f"(c[0]), "+f"(c[1]), "+f"(c[2]), "+f"(c[3])
        : "r"(a[0]), "r"(a[1]), "r"(a[2]), "r"(a[3]), "r"(b0), "r"(b1));
}
#define CP_COMMIT() asm volatile("cp.async.commit_group;" ::: "memory")
#define CP_WAIT1()  asm volatile("cp.async.wait_group 1;"  ::: "memory")
#define CP_WAIT0()  asm volatile("cp.async.wait_group 0;"  ::: "memory")

// ---------------------------------------------------------------- convert features -> tf32 (pad rows zero)
__global__ void k_convert_feats(const float* __restrict__ feats)
{
    const float4* f4 = (const float4*)feats;
    float4* o4 = (float4*)g_ftf;
    const int n4 = NS_PAD * NFEAT / 4;
    for (int i = blockIdx.x * blockDim.x + threadIdx.x; i < n4; i += gridDim.x * blockDim.x) {
        int row = i >> 6;                       // 64 float4 per row
        float4 o;
        if (row < NSAMP) {
            float4 v = f4[i];
            o.x = __uint_as_float(f2tf32(v.x));
            o.y = __uint_as_float(f2tf32(v.y));
            o.z = __uint_as_float(f2tf32(v.z));
            o.w = __uint_as_float(f2tf32(v.w));
        } else {
            o = make_float4(0.f, 0.f, 0.f, 0.f);
        }
        o4[i] = o;
    }
}

// ---------------------------------------------------------------- B k-quarter async load (32 KB)
__device__ __forceinline__ void ld_quarter(float* buf, int gt, int q, int tid)
{
    const float* src = g_ftf + (size_t)gt * TILE_N * NFEAT + q * 64;
    const uint32_t sbase = smem_u32(buf);
    #pragma unroll
    for (int i = 0; i < 8; i++) {
        int c  = i * THREADS + tid;             // float4 slot; 16 per 64-col row
        int rr = c >> 4;
        int cc = c & 15;
        uint32_t sa = sbase + (uint32_t)(rr * BQ_STRIDE + cc * 4) * 4u;
        const float* ga = src + (size_t)rr * NFEAT + cc * 4;
        asm volatile("cp.async.cg.shared.global [%0], [%1], 16;"
                     :: "r"(sa), "l"(ga) : "memory");
    }
}

// ---------------------------------------------------------------- main fused kernel
__global__ __launch_bounds__(THREADS, 1)
void k_main(const float* __restrict__ inputs)
{
    extern __shared__ float sm[];
    float* As  = sm;                        // [128][260]
    float* Bq0 = sm + A_FLOATS;             // [128][68] k-quarter buffer 0
    float* Bq1 = Bq0 + BQ_FLOATS;           // [128][68] k-quarter buffer 1

    const int tid = threadIdx.x;
    const int wid = tid >> 5;
    const int ln  = tid & 31;
    const int wm  = wid >> 1;               // m-tile: rows wm*32 .. +31 (0..3)
    const int wn  = wid & 1;                // n-half: cols wn*64 .. +63
    const int lg  = ln >> 2;                // mma groupID 0..7
    const int lt  = ln & 3;                 // mma tid-in-group 0..3

    const int r0  = blockIdx.x * M_CTA;
    const int gt0 = blockIdx.y * TPC;
    int T = TILES_TOT - gt0; if (T > TPC) T = TPC;

    // ---- load A: inputs * XSCALE, tf32-rounded, into padded smem
    {
        const float4* in4 = (const float4*)inputs;
        for (int i = tid; i < M_CTA * 64; i += THREADS) {
            int rr = i >> 6, cc = i & 63;
            float4 v = in4[(size_t)(r0 + rr) * 64 + cc];
            uint32_t* dst = (uint32_t*)(As + rr * A_STRIDE + cc * 4);
            dst[0] = f2tf32(v.x * XSCALE);
            dst[1] = f2tf32(v.y * XSCALE);
            dst[2] = f2tf32(v.z * XSCALE);
            dst[3] = f2tf32(v.w * XSCALE);
        }
    }

    // ---- prologue: first two k-quarters in flight
    ld_quarter(Bq0, gt0, 0, tid); CP_COMMIT();
    ld_quarter(Bq1, gt0, 1, tid); CP_COMMIT();

    float acc[2][8][4];
    #pragma unroll
    for (int mf = 0; mf < 2; mf++)
        #pragma unroll
        for (int nf = 0; nf < 8; nf++)
            #pragma unroll
            for (int j = 0; j < 4; j++) acc[mf][nf][j] = 0.0f;

    float m[4], s[4];   // per owned row slot: r = mf*2+hh
    #pragma unroll
    for (int r = 0; r < 4; r++) { m[r] = -3.0e38f; s[r] = 0.0f; }

    const uint32_t* Ap = (const uint32_t*)As;
    const int H = 4 * T;                    // k-quarters total

    for (int h = 0; h < H; h++) {
        if (h + 1 < H) CP_WAIT1(); else CP_WAIT0();   // quarter h resident
        __syncthreads();

        const uint32_t* Bp = (const uint32_t*)((h & 1) ? Bq1 : Bq0);
        const int q = h & 3;

        #pragma unroll
        for (int ks = 0; ks < 8; ks++) {
            const int kc = q * 64 + ks * 8 + lt;
            uint32_t a[2][4];
            #pragma unroll
            for (int mf = 0; mf < 2; mf++) {
                const int rb = wm * 32 + mf * 16 + lg;
                a[mf][0] = Ap[rb * A_STRIDE + kc];
                a[mf][1] = Ap[(rb + 8) * A_STRIDE + kc];
                a[mf][2] = Ap[rb * A_STRIDE + kc + 4];
                a[mf][3] = Ap[(rb + 8) * A_STRIDE + kc + 4];
            }
            const int kb = ks * 8 + lt;
            #pragma unroll
            for (int nf = 0; nf < 8; nf++) {
                const int nn = wn * 64 + nf * 8 + lg;
                uint32_t b0 = Bp[nn * BQ_STRIDE + kb];
                uint32_t b1 = Bp[nn * BQ_STRIDE + kb + 4];
                mma_tf32(acc[0][nf], a[0], b0, b1);
                mma_tf32(acc[1][nf], a[1], b0, b1);
            }
        }

        __syncthreads();                    // all warps done reading this buffer
        if (h + 2 < H) {                    // refill the buffer just consumed
            ld_quarter((h & 1) ? Bq1 : Bq0, gt0 + ((h + 2) >> 2), (h + 2) & 3, tid);
            CP_COMMIT();
        }

        if (q == 3) {
            // ---- tile epilogue: threshold-gated online logsumexp (base-2)
            #pragma unroll
            for (int mf = 0; mf < 2; mf++) {
                #pragma unroll
                for (int hh = 0; hh < 2; hh++) {
                    const int r = mf * 2 + hh;
                    float t0 = fmaxf(acc[mf][0][2*hh], acc[mf][0][2*hh+1]);
                    float t1 = fmaxf(acc[mf][1][2*hh], acc[mf][1][2*hh+1]);
                    float t2 = fmaxf(acc[mf][2][2*hh], acc[mf][2][2*hh+1]);
                    float t3 = fmaxf(acc[mf][3][2*hh], acc[mf][3][2*hh+1]);
                    float t4 = fmaxf(acc[mf][4][2*hh], acc[mf][4][2*hh+1]);
                    float t5 = fmaxf(acc[mf][5][2*hh], acc[mf][5][2*hh+1]);
                    float t6 = fmaxf(acc[mf][6][2*hh], acc[mf][6][2*hh+1]);
                    float t7 = fmaxf(acc[mf][7][2*hh], acc[mf][7][2*hh+1]);
                    float tmax = fmaxf(fmaxf(fmaxf(t0, t1), fmaxf(t2, t3)),
                                       fmaxf(fmaxf(t4, t5), fmaxf(t6, t7)));
                    if (tmax > m[r] - CUT) {        // rare slow path
                        float nm = fmaxf(m[r], tmax);
                        float add = 0.0f;
                        #pragma unroll
                        for (int nf = 0; nf < 8; nf++) {
                            add += ex2(acc[mf][nf][2*hh]   - nm);
                            add += ex2(acc[mf][nf][2*hh+1] - nm);
                        }
                        s[r] = s[r] * ex2(m[r] - nm) + add;
                        m[r] = nm;
                    }
                }
            }
            #pragma unroll
            for (int mf = 0; mf < 2; mf++)
                #pragma unroll
                for (int nf = 0; nf < 8; nf++)
                    #pragma unroll
                    for (int j = 0; j < 4; j++) acc[mf][nf][j] = 0.0f;
        }
    }

    // ---- merge (m,s) across the 4 lanes (lt) sharing each row; store per n-half
    #pragma unroll
    for (int r = 0; r < 4; r++) {
        float mm = m[r], ss = s[r];
        #pragma unroll
        for (int off = 1; off <= 2; off <<= 1) {
            float om = __shfl_xor_sync(0xffffffffu, mm, off);
            float os = __shfl_xor_sync(0xffffffffu, ss, off);
            float nm = fmaxf(mm, om);
            ss = ss * ex2(mm - nm) + os * ex2(om - nm);
            mm = nm;
        }
        if (lt == 0) {
            const int row = r0 + wm * 32 + (r >> 1) * 16 + (r & 1) * 8 + lg;
            g_partials[((size_t)row * NCHUNK + blockIdx.y) * 2 + wn] = make_float2(mm, ss);
        }
    }
}

// ---------------------------------------------------------------- combine + mean
__global__ void k_combine(const float* __restrict__ inputs,
                          const float* __restrict__ feats,
                          const int* __restrict__ targets)
{
    const int row = blockIdx.x;
    const int t   = threadIdx.x;

    float m = -3.0e38f, s = 0.0f;                  // base-2
    for (int c = t; c < NCHUNK * 2; c += 32) {
        float2 p = g_partials[(size_t)row * NCHUNK * 2 + c];
        float nm = fmaxf(m, p.x);
        s = s * ex2(m - nm) + p.y * ex2(p.x - nm);
        m = nm;
    }
    #pragma unroll
    for (int off = 16; off >= 1; off >>= 1) {
        float om = __shfl_xor_sync(0xffffffffu, m, off);
        float os = __shfl_xor_sync(0xffffffffu, s, off);
        float nm = fmaxf(m, om);
        s = s * ex2(m - nm) + os * ex2(om - nm);
        m = nm;
    }

    // exact target logit in fp32
    int tg = targets[row];
    tg = (tg < 0) ? 0 : ((tg >= NSAMP) ? (NSAMP - 1) : tg);
    const float* ir = inputs + (size_t)row * NFEAT;
    const float* fr = feats  + (size_t)tg  * NFEAT;
    float d = 0.0f;
    for (int k = t; k < NFEAT; k += 32) d = fmaf(ir[k], fr[k], d);
    #pragma unroll
    for (int off = 16; off >= 1; off >>= 1)
        d += __shfl_xor_sync(0xffffffffu, d, off);

    if (t == 0)
        g_nll[row] = LN2 * (m + log2f(s)) - d * INV_TEMP;
}

__global__ void k_mean(float* __restrict__ out)
{
    __shared__ float red[256];
    const int t = threadIdx.x;
    float a = 0.0f;
    for (int i = t; i < B_ROWS; i += 256) a += g_nll[i];
    red[t] = a;
    __syncthreads();
    for (int w = 128; w > 0; w >>= 1) {
        if (t < w) red[t] += red[t + w];
        __syncthreads();
    }
    if (t == 0) out[0] = red[0] * (1.0f / B_ROWS);
}

// ---------------------------------------------------------------- launch
extern "C" void kernel_launch(void* const* d_in, const int* in_sizes, int n_in,
                              void* d_out, int out_size)
{
    const float* inputs  = (const float*)d_in[0];
    const int*   targets = (const int*)d_in[1];
    const float* feats   = (const float*)d_in[2];

    cudaFuncSetAttribute(k_main, cudaFuncAttributeMaxDynamicSharedMemorySize, SMEM_TOTAL);

    k_convert_feats<<<2048, 256>>>(feats);

    dim3 grid(NROWT, NCHUNK);               // row-tile fastest -> B shared in L2
    k_main<<<grid, THREADS, SMEM_TOTAL>>>(inputs);

    k_combine<<<B_ROWS, 32>>>(inputs, feats, targets);
    k_mean<<<1, 256>>>((float*)d_out);
}